// round 17
// baseline (speedup 1.0000x reference)
#include <cuda_runtime.h>
#include <cuda_bf16.h>
#include <cstdint>

#define N_NODES 100000
#define N_EDGES 200000
#define IN_DIM  384
#define HID     128

// ---------------- device scratch (no allocations allowed) ----------------
__device__ float g_PR [(size_t)N_NODES * 256];   // [P | R] per layer, reused
__device__ float g_h  [(size_t)N_NODES * HID];   // layer-1 output (fp32)
__device__ float g_agg[(size_t)N_NODES * HID];
__device__ int   g_cnt[N_NODES];
// Pre-split transposed weights: B[n][k] with n in [0,256) = [Wl | Wr] cols
__device__ __nv_bfloat16 g_B1h[256 * IN_DIM], g_B1l[256 * IN_DIM];
__device__ __nv_bfloat16 g_B2h[256 * HID],    g_B2l[256 * HID];

__device__ __forceinline__ int clampN(int v) {
    return v < 0 ? 0 : (v >= N_NODES ? N_NODES - 1 : v);
}
__device__ __forceinline__ uint32_t smem_u32(const void* p) {
    return (uint32_t)__cvta_generic_to_shared(p);
}
__device__ __forceinline__ uint32_t pack2(__nv_bfloat16 a, __nv_bfloat16 b) {
    return (uint32_t)__bfloat16_as_ushort(a) | ((uint32_t)__bfloat16_as_ushort(b) << 16);
}

// ---------------- family-safe tensor / async ops (sm_80+ PTX) ----------
__device__ __forceinline__ void ldsm4(uint32_t* r, uint32_t addr) {
    asm volatile("ldmatrix.sync.aligned.m8n8.x4.shared.b16 {%0,%1,%2,%3}, [%4];"
                 : "=r"(r[0]), "=r"(r[1]), "=r"(r[2]), "=r"(r[3]) : "r"(addr));
}
__device__ __forceinline__ void mma16816(float* c, const uint32_t* a,
                                         uint32_t b0, uint32_t b1) {
    asm volatile(
        "mma.sync.aligned.m16n8k16.row.col.f32.bf16.bf16.f32 "
        "{%0,%1,%2,%3}, {%4,%5,%6,%7}, {%8,%9}, {%0,%1,%2,%3};"
        : "+f"(c[0]), "+f"(c[1]), "+f"(c[2]), "+f"(c[3])
        : "r"(a[0]), "r"(a[1]), "r"(a[2]), "r"(a[3]), "r"(b0), "r"(b1));
}
__device__ __forceinline__ void cpasync16(uint32_t s, const void* g) {
    asm volatile("cp.async.cg.shared.global [%0], [%1], 16;" :: "r"(s), "l"(g));
}
__device__ __forceinline__ void cpcommit() {
    asm volatile("cp.async.commit_group;" ::: "memory");
}
template<int N> __device__ __forceinline__ void cpwait() {
    asm volatile("cp.async.wait_group %0;" :: "n"(N) : "memory");
}

// =====================================================================
// Split-bf16 HMMA GEMM, fully double-buffered (A and B), ONE sync/chunk:
//   iter c: cp.async B(c+1) | convert+STS A(c+1) (regs->smem, other stage)
//           | LDG A(c+2)->regs | compute(c) | wait+sync
// C[128-row tile, 128-col half] = A @ (Wl or Wr); grid (782, 2).
// 8 warps: 4 along M x 2 along N; BK=32; AhBh+AhBl+AlBh, fp32 acc.
// =====================================================================
#define SPAD 40          // bf16 row stride -> conflict-free ldmatrix
#define TILE_E 5120      // 128 * SPAD bf16 elements per tile
#define GEMM_DSMEM (8 * TILE_E * 2)   // 8 tiles = 81920 B

template<int K, int LAYER>
__global__ __launch_bounds__(256, 2) void gemm_mma(const float* __restrict__ Aext)
{
    extern __shared__ __align__(16) __nv_bfloat16 dsm[];
    // stages: A{h,l} x2, B{h,l} x2
    __nv_bfloat16* const AhS[2] = { dsm,               dsm + 2 * TILE_E };
    __nv_bfloat16* const AlS[2] = { dsm + TILE_E,      dsm + 3 * TILE_E };
    __nv_bfloat16* const BhS[2] = { dsm + 4 * TILE_E,  dsm + 6 * TILE_E };
    __nv_bfloat16* const BlS[2] = { dsm + 5 * TILE_E,  dsm + 7 * TILE_E };

    const float* __restrict__ A = (LAYER == 1) ? Aext : g_h;
    const __nv_bfloat16* __restrict__ Bhg = (LAYER == 1) ? g_B1h : g_B2h;
    const __nv_bfloat16* __restrict__ Blg = (LAYER == 1) ? g_B1l : g_B2l;

    const int tid = threadIdx.x;
    const int wid = tid >> 5, lid = tid & 31;
    const int m0  = blockIdx.x * 128;
    const int by  = blockIdx.y;             // 0 = Wl half, 1 = Wr half
    const int r0  = (wid & 3) * 32;         // warp M offset
    const int n0  = (wid >> 2) * 64;        // warp N offset (local)

    float acc[2][8][4];
#pragma unroll
    for (int s = 0; s < 2; s++)
#pragma unroll
        for (int t = 0; t < 8; t++)
#pragma unroll
            for (int q = 0; q < 4; q++) acc[s][t][q] = 0.f;

    // ldmatrix lane->row/col mapping
    const int lq = lid >> 3, ll = lid & 7;
    const int a_row_off = (lq & 1) * 8 + ll;
    const int a_col_off = (lq >> 1) * 8;
    const int b_row_off = (lq >> 1) * 8 + ll;
    const int b_col_off = (lq & 1) * 8;

    float4 areg[4];
    const int CH = K / 32;

    // helpers as lambdas ------------------------------------------------
    auto ldgA = [&](int c) {
#pragma unroll
        for (int i = 0; i < 4; ++i) {
            int idx = tid + i * 256;
            int r = idx >> 3, j4 = idx & 7;
            int gm = m0 + r;
            areg[i] = (gm < N_NODES)
                    ? *(const float4*)(A + (size_t)gm * K + c * 32 + j4 * 4)
                    : make_float4(0.f, 0.f, 0.f, 0.f);
        }
    };
    auto cvtA = [&](int stage) {
        __nv_bfloat16* const ah = AhS[stage];
        __nv_bfloat16* const al = AlS[stage];
#pragma unroll
        for (int i = 0; i < 4; ++i) {
            int idx = tid + i * 256;
            int r = idx >> 3, j4 = idx & 7;
            float4 v = areg[i];
            __nv_bfloat16 h0 = __float2bfloat16(v.x), h1 = __float2bfloat16(v.y);
            __nv_bfloat16 h2 = __float2bfloat16(v.z), h3 = __float2bfloat16(v.w);
            __nv_bfloat16 l0 = __float2bfloat16(v.x - __bfloat162float(h0));
            __nv_bfloat16 l1 = __float2bfloat16(v.y - __bfloat162float(h1));
            __nv_bfloat16 l2 = __float2bfloat16(v.z - __bfloat162float(h2));
            __nv_bfloat16 l3 = __float2bfloat16(v.w - __bfloat162float(h3));
            int o = r * SPAD + j4 * 4;
            *(uint2*)(ah + o) = make_uint2(pack2(h0, h1), pack2(h2, h3));
            *(uint2*)(al + o) = make_uint2(pack2(l0, l1), pack2(l2, l3));
        }
    };
    auto cpB = [&](int c) {
        const uint32_t sbh = smem_u32(BhS[c & 1]);
        const uint32_t sbl = smem_u32(BlS[c & 1]);
#pragma unroll
        for (int i = 0; i < 2; ++i) {
            int idx = tid + i * 256;
            int n = idx >> 2, j = idx & 3;
            size_t go = (size_t)(by * 128 + n) * K + c * 32 + j * 8;
            uint32_t so = (uint32_t)(n * SPAD + j * 8) * 2;
            cpasync16(sbh + so, Bhg + go);
            cpasync16(sbl + so, Blg + go);
        }
        cpcommit();
    };

    // ---------------- prologue ----------------
    ldgA(0);
    cpB(0);
    cvtA(0);
    if (CH > 1) ldgA(1);
    cpwait<0>();
    __syncthreads();

    // ---------------- main loop: ONE sync per chunk ----------------
    for (int c = 0; c < CH; ++c) {
        if (c + 1 < CH) {
            cpB(c + 1);          // writes stage (c+1)&1: last read ended at sync
            cvtA((c + 1) & 1);   // from areg (LDG'd one iter ago)
        }
        if (c + 2 < CH) ldgA(c + 2);   // latency hidden behind compute below

        // ---- compute chunk c ----
        const uint32_t sAh = smem_u32(AhS[c & 1]);
        const uint32_t sAl = smem_u32(AlS[c & 1]);
        const uint32_t sBh = smem_u32(BhS[c & 1]);
        const uint32_t sBl = smem_u32(BlS[c & 1]);
#pragma unroll
        for (int ks = 0; ks < 2; ++ks) {
            const int k0 = ks * 16;
            uint32_t ah[2][4], al[2][4];
#pragma unroll
            for (int s = 0; s < 2; ++s) {
                uint32_t off = (uint32_t)((r0 + s * 16 + a_row_off) * SPAD
                                          + k0 + a_col_off) * 2;
                ldsm4(ah[s], sAh + off);
                ldsm4(al[s], sAl + off);
            }
#pragma unroll
            for (int g = 0; g < 4; ++g) {
                uint32_t bh4[4], bl4[4];
                uint32_t off = (uint32_t)((n0 + g * 16 + b_row_off) * SPAD
                                          + k0 + b_col_off) * 2;
                ldsm4(bh4, sBh + off);
                ldsm4(bl4, sBl + off);
#pragma unroll
                for (int h = 0; h < 2; ++h) {
                    int t = g * 2 + h;
#pragma unroll
                    for (int s = 0; s < 2; ++s) {
                        mma16816(acc[s][t], ah[s], bh4[h*2], bh4[h*2+1]);
                        mma16816(acc[s][t], ah[s], bl4[h*2], bl4[h*2+1]);
                        mma16816(acc[s][t], al[s], bh4[h*2], bh4[h*2+1]);
                    }
                }
            }
        }
        if (c + 1 < CH) cpwait<0>();
        __syncthreads();
    }

    // ---- epilogue: acc -> g_PR (rows x 256), this CTA's 128-col half ----
#pragma unroll
    for (int s = 0; s < 2; ++s) {
        int row = m0 + r0 + s * 16 + (lid >> 2);
#pragma unroll
        for (int t = 0; t < 8; ++t) {
            int col = by * 128 + n0 + t * 8 + (lid & 3) * 2;
            if (row < N_NODES)
                *(float2*)(g_PR + (size_t)row * 256 + col) =
                    make_float2(acc[s][t][0], acc[s][t][1]);
            if (row + 8 < N_NODES)
                *(float2*)(g_PR + (size_t)(row + 8) * 256 + col) =
                    make_float2(acc[s][t][2], acc[s][t][3]);
        }
    }
}

// =====================================================================
// Weight split/transpose, both layers in one launch (keeps gemm_mma 4th).
// =====================================================================
__global__ void split_w_all(const float* __restrict__ W1l, const float* __restrict__ W1r,
                            const float* __restrict__ W2l, const float* __restrict__ W2r) {
    int idx = blockIdx.x * blockDim.x + threadIdx.x;
    if (idx < 256 * IN_DIM) {
        int n = idx / IN_DIM, k = idx - n * IN_DIM;
        float v = (n < 128) ? W1l[(size_t)k * HID + n] : W1r[(size_t)k * HID + (n - 128)];
        __nv_bfloat16 h = __float2bfloat16(v);
        g_B1h[idx] = h;
        g_B1l[idx] = __float2bfloat16(v - __bfloat162float(h));
    } else if (idx < 256 * IN_DIM + 256 * HID) {
        int j = idx - 256 * IN_DIM;
        int n = j / HID, k = j - n * HID;
        float v = (n < 128) ? W2l[(size_t)k * HID + n] : W2r[(size_t)k * HID + (n - 128)];
        __nv_bfloat16 h = __float2bfloat16(v);
        g_B2h[j] = h;
        g_B2l[j] = __float2bfloat16(v - __bfloat162float(h));
    }
}

// =====================================================================
// Helper kernels
// =====================================================================
__global__ void zero_kernel() {
    int idx = blockIdx.x * blockDim.x + threadIdx.x;
    if (idx < N_NODES * (HID / 4))
        ((float4*)g_agg)[idx] = make_float4(0.f, 0.f, 0.f, 0.f);
    if (idx < N_NODES) g_cnt[idx] = 0;
}

__global__ void count_kernel(const int* __restrict__ ei) {
    int e = blockIdx.x * blockDim.x + threadIdx.x;
    if (e < N_EDGES) atomicAdd(&g_cnt[clampN(ei[N_EDGES + e])], 1);
}

// agg[dst] += P[src] via vectorized red.global.add.v4.f32 (PTX 8.1+, sm_90+)
__global__ void scatter_kernel(const int* __restrict__ ei) {
    int idx = blockIdx.x * blockDim.x + threadIdx.x;
    if (idx >= N_EDGES * 32) return;
    int e = idx >> 5, q = idx & 31;
    int src = clampN(ei[e]);
    int dst = clampN(ei[N_EDGES + e]);
    float4 v = *(const float4*)(g_PR + (size_t)src * 256 + q * 4);
    float* d = g_agg + (size_t)dst * HID + q * 4;
    asm volatile("red.global.add.v4.f32 [%0], {%1, %2, %3, %4};"
                 :: "l"(d), "f"(v.x), "f"(v.y), "f"(v.z), "f"(v.w) : "memory");
}

template<bool L2>
__global__ void combine_kernel(const float* __restrict__ bias,
                               float* __restrict__ outp) {
    int idx = blockIdx.x * blockDim.x + threadIdx.x;
    if (idx >= N_NODES * 32) return;
    float* __restrict__ o = L2 ? outp : g_h;
    int n = idx >> 5, q = idx & 31;
    int c = g_cnt[n];
    float inv = 1.0f / (float)(c > 0 ? c : 1);
    float4 s  = ((const float4*)g_agg)[idx];
    float4 r  = *(const float4*)(g_PR + (size_t)n * 256 + 128 + q * 4);
    float4 bb = *(const float4*)(bias + q * 4);
    float4 v;
    v.x = fmaf(s.x, inv, bb.x + r.x);
    v.y = fmaf(s.y, inv, bb.y + r.y);
    v.z = fmaf(s.z, inv, bb.z + r.z);
    v.w = fmaf(s.w, inv, bb.w + r.w);
    if (!L2) {
        v.x = fmaxf(v.x, 0.f); v.y = fmaxf(v.y, 0.f);
        v.z = fmaxf(v.z, 0.f); v.w = fmaxf(v.w, 0.f);
        ((float4*)g_agg)[idx] = make_float4(0.f, 0.f, 0.f, 0.f);
    }
    ((float4*)o)[idx] = v;
}

// =====================================================================
extern "C" void kernel_launch(void* const* d_in, const int* in_sizes, int n_in,
                              void* d_out, int out_size) {
    const float* x   = (const float*)d_in[0];
    const int*   ei  = (const int*)d_in[1];      // int64 in ref -> int32 here
    const float* W1l = (const float*)d_in[2];
    const float* b1  = (const float*)d_in[3];
    const float* W1r = (const float*)d_in[4];
    const float* W2l = (const float*)d_in[5];
    const float* b2  = (const float*)d_in[6];
    const float* W2r = (const float*)d_in[7];
    float* out = (float*)d_out;

    cudaFuncSetAttribute(gemm_mma<IN_DIM, 1>,
                         cudaFuncAttributeMaxDynamicSharedMemorySize, GEMM_DSMEM);
    cudaFuncSetAttribute(gemm_mma<HID, 2>,
                         cudaFuncAttributeMaxDynamicSharedMemorySize, GEMM_DSMEM);

    const int T = 256;
    const int gM       = (N_NODES + 127) / 128;      // 782
    const int gZero    = (N_NODES * 32 + T - 1) / T;
    const int gCount   = (N_EDGES + T - 1) / T;
    const int gScatter = (N_EDGES * 32 + T - 1) / T;
    const int nSplit   = 256 * IN_DIM + 256 * HID;

    zero_kernel<<<gZero, T>>>();                                  // 1
    count_kernel<<<gCount, T>>>(ei);                              // 2
    split_w_all<<<(nSplit + T - 1) / T, T>>>(W1l, W1r, W2l, W2r); // 3

    // Layer 1: PR = x @ [W1l | W1r]
    gemm_mma<IN_DIM, 1><<<dim3(gM, 2), T, GEMM_DSMEM>>>(x);       // 4 <- profiled
    scatter_kernel<<<gScatter, T>>>(ei);                          // 5
    combine_kernel<false><<<gZero, T>>>(b1, nullptr);             // 6 -> g_h

    // Layer 2: PR = h @ [W2l | W2r]
    gemm_mma<HID, 2><<<dim3(gM, 2), T, GEMM_DSMEM>>>(nullptr);    // 7
    scatter_kernel<<<gScatter, T>>>(ei);                          // 8
    combine_kernel<true><<<gZero, T>>>(b2, out);                  // 9 -> d_out
}